// round 13
// baseline (speedup 1.0000x reference)
#include <cuda_runtime.h>
#include <cuda_fp16.h>
#include <mma.h>
#include <cstdint>
using namespace nvcuda;

#define EPS 1e-5f
static constexpr int D = 512, COLS = 1024, B = 256, OUTC = 250, MAXT = 784;

__device__ float g_gate[MAXT * 128];
__device__ int   g_segoff[257];
__device__ float g_pooled[B * D];
__device__ float g_pn[B * D];
__device__ float g_z[B * COLS];
__device__ float g_y[(size_t)MAXT * 128 * 1024];
// fragment-packed operands: 16B per lane per fragment
__device__ uint4 g_pa[(size_t)MAXT * 32 * 8 * 32];    // [tile][ks 32][mf 8][lane]  (A fp16)
__device__ uint4 g_pb[32 * 64 * 32];                  // [ks 32][nf 64][lane]       (W fp16)

// ---------- prep_x_pack: fp32 x -> fp16 -> wmma A fragments (packed) ----------
static constexpr int XP = 264;                        // smem row stride (half elems)
static constexpr uint32_t SMX = 128u * XP * 2;        // 67584 bytes

__global__ __launch_bounds__(256) void prep_x_pack(const float* __restrict__ x, int n) {
    extern __shared__ char sm[];
    __half* sh = (__half*)sm;
    const int tile = blockIdx.x, tid = threadIdx.x, wid = tid >> 5, lane = tid & 31;
    for (int kh = 0; kh < 2; ++kh) {
        __syncthreads();
        for (int i = tid; i < 8192; i += 256) {          // 128 rows x 64 float4
            int r = i >> 6, c4 = i & 63;
            int row = tile * 128 + r;
            float4 v = (row < n) ? *(const float4*)(x + (size_t)row * 512 + kh * 256 + c4 * 4)
                                 : make_float4(0.f, 0.f, 0.f, 0.f);
            *(__half2*)(sh + r * XP + c4 * 4)     = __floats2half2_rn(v.x, v.y);
            *(__half2*)(sh + r * XP + c4 * 4 + 2) = __floats2half2_rn(v.z, v.w);
        }
        __syncthreads();
        for (int ks = 0; ks < 16; ++ks) {
            wmma::fragment<wmma::matrix_a, 16, 16, 16, __half, wmma::row_major> f;
            wmma::load_matrix_sync(f, sh + (wid * 16) * XP + ks * 16, XP);
            g_pa[(((size_t)tile * 32 + kh * 16 + ks) * 8 + wid) * 32 + lane] =
                *(const uint4*)&f.x[0];
        }
    }
}

// ---------- prep_w_pack: fp32 W[1024,512] -> fp16 -> wmma B fragments ----------
static constexpr int WP = 520;
static constexpr uint32_t SMW = 64u * WP * 2;         // 66560 bytes

__global__ __launch_bounds__(256) void prep_w_pack(const float* __restrict__ w) {
    extern __shared__ char sm[];
    __half* sh = (__half*)sm;
    const int cb = blockIdx.x, tid = threadIdx.x, wid = tid >> 5, lane = tid & 31;
    for (int i = tid; i < 8192; i += 256) {              // 64 cols x 128 float4 (K=512)
        int c = i >> 7, k4 = i & 127;
        float4 v = *(const float4*)(w + (size_t)(cb * 64 + c) * 512 + k4 * 4);
        *(__half2*)(sh + c * WP + k4 * 4)     = __floats2half2_rn(v.x, v.y);
        *(__half2*)(sh + c * WP + k4 * 4 + 2) = __floats2half2_rn(v.z, v.w);
    }
    __syncthreads();
    for (int idx = wid; idx < 128; idx += 8) {           // 4 nf x 32 ks
        int ks = idx & 31, nf = idx >> 5;
        wmma::fragment<wmma::matrix_b, 16, 16, 16, __half, wmma::col_major> f;
        wmma::load_matrix_sync(f, sh + nf * 16 * WP + ks * 16, WP);
        g_pb[((size_t)ks * 64 + cb * 4 + nf) * 32 + lane] = *(const uint4*)&f.x[0];
    }
}

// ---------- phase A GEMM: fragment-direct fp16, A-prefetch pipeline ----------
// CTA 128x256 (8 warps, 2m x 4n), warp tile 64x64. grid (4, tiles).
__global__ __launch_bounds__(256, 1) void gemm_k() {
    const int cb = blockIdx.x, tile = blockIdx.y;
    const int wid = threadIdx.x >> 5, lane = threadIdx.x & 31;
    const int wm = wid & 1, wn = wid >> 1;
    const int mfb = wm * 4, nfb = cb * 16 + wn * 4;

    wmma::fragment<wmma::accumulator, 16, 16, 16, float> acc[4][4];
    #pragma unroll
    for (int mt = 0; mt < 4; ++mt)
        #pragma unroll
        for (int nt = 0; nt < 4; ++nt) wmma::fill_fragment(acc[mt][nt], 0.f);

    const uint4* __restrict__ pa = g_pa + (size_t)tile * 32 * 8 * 32;
    const uint4* __restrict__ pb = g_pb;

    uint4 ra[4];                                        // A prefetch buffer (ks current)
    #pragma unroll
    for (int mt = 0; mt < 4; ++mt)
        ra[mt] = __ldg(&pa[(0 * 8 + mfb + mt) * 32 + lane]);

    #pragma unroll 2
    for (int ks = 0; ks < 32; ++ks) {
        uint4 rn[4];
        if (ks + 1 < 32) {
            #pragma unroll
            for (int mt = 0; mt < 4; ++mt)
                rn[mt] = __ldg(&pa[((ks + 1) * 8 + mfb + mt) * 32 + lane]);
        }
        wmma::fragment<wmma::matrix_a, 16, 16, 16, __half, wmma::row_major> a[4];
        wmma::fragment<wmma::matrix_b, 16, 16, 16, __half, wmma::col_major> b[4];
        #pragma unroll
        for (int mt = 0; mt < 4; ++mt) *(uint4*)&a[mt].x[0] = ra[mt];
        #pragma unroll
        for (int nt = 0; nt < 4; ++nt)
            *(uint4*)&b[nt].x[0] = __ldg(&pb[(ks * 64 + nfb + nt) * 32 + lane]);
        #pragma unroll
        for (int mt = 0; mt < 4; ++mt)
            #pragma unroll
            for (int nt = 0; nt < 4; ++nt)
                wmma::mma_sync(acc[mt][nt], a[mt], b[nt], acc[mt][nt]);
        #pragma unroll
        for (int mt = 0; mt < 4; ++mt) ra[mt] = rn[mt];
    }
    #pragma unroll
    for (int mt = 0; mt < 4; ++mt)
        #pragma unroll
        for (int nt = 0; nt < 4; ++nt) {
            size_t row0 = (size_t)tile * 128 + wm * 64 + mt * 16;
            int col0 = cb * 256 + wn * 64 + nt * 16;
            wmma::store_matrix_sync(g_y + row0 * 1024 + col0, acc[mt][nt], 1024,
                                    wmma::mem_row_major);
        }
}

// ---------- LN + ReLU + gate dot (one warp per row) ----------
__global__ __launch_bounds__(256) void ln_gate_k(
    const float* __restrict__ bias, const float* __restrict__ lng,
    const float* __restrict__ lnb, const float* __restrict__ W2,
    const float* __restrict__ b2, int N)
{
    const int row = blockIdx.x * 8 + (threadIdx.x >> 5);
    if (row >= N) return;
    const int lane = threadIdx.x & 31;
    const float4* yr = (const float4*)(g_y + (size_t)row * 1024);
    const float4* b4 = (const float4*)bias;
    float4 v[8]; float s1 = 0.f, s2 = 0.f;
    #pragma unroll
    for (int j = 0; j < 8; ++j) {
        int i = j * 32 + lane;
        float4 t = yr[i], bb = b4[i];
        t.x += bb.x; t.y += bb.y; t.z += bb.z; t.w += bb.w;
        v[j] = t;
        s1 += t.x + t.y + t.z + t.w;
        s2 += t.x * t.x + t.y * t.y + t.z * t.z + t.w * t.w;
    }
    #pragma unroll
    for (int o = 16; o > 0; o >>= 1) {
        s1 += __shfl_xor_sync(~0u, s1, o);
        s2 += __shfl_xor_sync(~0u, s2, o);
    }
    float mean = s1 * (1.f / 1024.f);
    float rstd = rsqrtf(fmaxf(s2 * (1.f / 1024.f) - mean * mean, 0.f) + EPS);
    float gd = 0.f;
    #pragma unroll
    for (int j = 0; j < 8; ++j) {
        int i = j * 32 + lane;
        float4 g = ((const float4*)lng)[i], lb = ((const float4*)lnb)[i],
               w = ((const float4*)W2)[i];
        float t;
        t = (v[j].x - mean) * rstd * g.x + lb.x; gd += fmaxf(t, 0.f) * w.x;
        t = (v[j].y - mean) * rstd * g.y + lb.y; gd += fmaxf(t, 0.f) * w.y;
        t = (v[j].z - mean) * rstd * g.z + lb.z; gd += fmaxf(t, 0.f) * w.z;
        t = (v[j].w - mean) * rstd * g.w + lb.w; gd += fmaxf(t, 0.f) * w.w;
    }
    #pragma unroll
    for (int o = 16; o > 0; o >>= 1) gd += __shfl_xor_sync(~0u, gd, o);
    if (lane == 0) g_gate[row] = gd + b2[0];
}

// ---------- tail (proven) ----------
__global__ void segoff_k(const int* __restrict__ ids, int N) {
    int b = threadIdx.x; if (b > B) return;
    int lo = 0, hi = N;
    while (lo < hi) { int m = (lo + hi) >> 1; if (ids[m] < b) lo = m + 1; else hi = m; }
    g_segoff[b] = lo;
}
__global__ __launch_bounds__(256) void segpool_k(const float* __restrict__ x) {
    __shared__ float red[32], sw[256], s_m, s_i;
    const int b = blockIdx.x, tid = threadIdx.x, lane = tid & 31, warp = tid >> 5;
    const int s = g_segoff[b], e = g_segoff[b + 1];
    float m = -3.4e38f;
    for (int i = s + tid; i < e; i += 256) m = fmaxf(m, g_gate[i]);
    for (int o = 16; o > 0; o >>= 1) m = fmaxf(m, __shfl_xor_sync(~0u, m, o));
    if (lane == 0) red[warp] = m;
    __syncthreads();
    if (tid < 32) {
        float v = (tid < 8) ? red[tid] : -3.4e38f;
        for (int o = 4; o > 0; o >>= 1) v = fmaxf(v, __shfl_xor_sync(~0u, v, o));
        if (tid == 0) s_m = v;
    }
    __syncthreads(); m = s_m;
    float ss = 0.f;
    for (int i = s + tid; i < e; i += 256) ss += expf(g_gate[i] - m);
    for (int o = 16; o > 0; o >>= 1) ss += __shfl_xor_sync(~0u, ss, o);
    __syncthreads();
    if (lane == 0) red[warp] = ss;
    __syncthreads();
    if (tid < 32) {
        float v = (tid < 8) ? red[tid] : 0.f;
        for (int o = 4; o > 0; o >>= 1) v += __shfl_xor_sync(~0u, v, o);
        if (tid == 0) s_i = (v > 0.f) ? 1.f / v : 0.f;
    }
    __syncthreads();
    const float inv = s_i;
    float2 acc = make_float2(0.f, 0.f);
    for (int base = s; base < e; base += 256) {
        int i = base + tid;
        sw[tid] = (i < e) ? expf(g_gate[i] - m) * inv : 0.f;
        __syncthreads();
        int cnt = min(256, e - base);
        #pragma unroll 4
        for (int r = 0; r < cnt; ++r) {
            float w = sw[r];
            float2 xv = *(const float2*)(x + (size_t)(base + r) * D + 2 * tid);
            acc.x += w * xv.x; acc.y += w * xv.y;
        }
        __syncthreads();
    }
    *(float2*)(g_pooled + b * D + 2 * tid) = acc;
}
__global__ __launch_bounds__(256) void poolln_k(const float* __restrict__ g, const float* __restrict__ bt) {
    __shared__ float red[64]; __shared__ float sm, sr;
    const int b = blockIdx.x, tid = threadIdx.x, lane = tid & 31, warp = tid >> 5;
    float v0 = g_pooled[b * D + tid], v1 = g_pooled[b * D + 256 + tid];
    float s1 = v0 + v1, s2 = v0 * v0 + v1 * v1;
    for (int o = 16; o > 0; o >>= 1) { s1 += __shfl_xor_sync(~0u, s1, o); s2 += __shfl_xor_sync(~0u, s2, o); }
    if (lane == 0) { red[warp] = s1; red[8 + warp] = s2; }
    __syncthreads();
    if (tid < 32) {
        float a1 = (tid < 8) ? red[tid] : 0.f, a2 = (tid < 8) ? red[8 + tid] : 0.f;
        for (int o = 4; o > 0; o >>= 1) { a1 += __shfl_xor_sync(~0u, a1, o); a2 += __shfl_xor_sync(~0u, a2, o); }
        if (tid == 0) {
            float mn = a1 * (1.f / D);
            sm = mn; sr = rsqrtf(fmaxf(a2 * (1.f / D) - mn * mn, 0.f) + EPS);
        }
    }
    __syncthreads();
    g_pn[b * D + tid]       = (v0 - sm) * sr * g[tid]       + bt[tid];
    g_pn[b * D + 256 + tid] = (v1 - sm) * sr * g[tid + 256] + bt[tid + 256];
}
__global__ __launch_bounds__(256) void cls_hidden_k(const float* __restrict__ W1, const float* __restrict__ b1,
                                                    const float* __restrict__ g, const float* __restrict__ bt) {
    __shared__ float sp[512]; __shared__ float red[64]; __shared__ float sm, sr;
    const int b = blockIdx.x, tid = threadIdx.x, lane = tid & 31, warp = tid >> 5;
    for (int i = tid; i < 512; i += 256) sp[i] = g_pn[b * D + i];
    __syncthreads();
    float v[4]; float s1 = 0.f, s2 = 0.f;
    #pragma unroll
    for (int cc = 0; cc < 4; ++cc) {
        int c = tid * 4 + cc;
        const float4* w = (const float4*)(W1 + (size_t)c * 512);
        const float4* p = (const float4*)sp;
        float a = b1[c];
        #pragma unroll 4
        for (int k = 0; k < 128; ++k) {
            float4 wv = w[k], pv = p[k];
            a += wv.x * pv.x + wv.y * pv.y + wv.z * pv.z + wv.w * pv.w;
        }
        v[cc] = a; s1 += a; s2 += a * a;
    }
    for (int o = 16; o > 0; o >>= 1) { s1 += __shfl_xor_sync(~0u, s1, o); s2 += __shfl_xor_sync(~0u, s2, o); }
    if (lane == 0) { red[warp] = s1; red[8 + warp] = s2; }
    __syncthreads();
    if (tid < 32) {
        float a1 = (tid < 8) ? red[tid] : 0.f, a2 = (tid < 8) ? red[8 + tid] : 0.f;
        for (int o = 4; o > 0; o >>= 1) { a1 += __shfl_xor_sync(~0u, a1, o); a2 += __shfl_xor_sync(~0u, a2, o); }
        if (tid == 0) {
            float mn = a1 * (1.f / COLS);
            sm = mn; sr = rsqrtf(fmaxf(a2 * (1.f / COLS) - mn * mn, 0.f) + EPS);
        }
    }
    __syncthreads();
    #pragma unroll
    for (int cc = 0; cc < 4; ++cc) {
        int c = tid * 4 + cc;
        g_z[(size_t)b * COLS + c] = fmaxf((v[cc] - sm) * sr * g[c] + bt[c], 0.f);
    }
}
__global__ __launch_bounds__(256) void logits_k(const float* __restrict__ W2, const float* __restrict__ b2,
                                                float* __restrict__ out) {
    __shared__ float sz[COLS];
    const int b = blockIdx.x, tid = threadIdx.x;
    for (int i = tid; i < COLS; i += 256) sz[i] = g_z[(size_t)b * COLS + i];
    __syncthreads();
    if (tid < OUTC) {
        const float4* wr = (const float4*)(W2 + (size_t)tid * COLS);
        const float4* zr = (const float4*)sz;
        float acc = 0.f;
        #pragma unroll 4
        for (int k = 0; k < COLS / 4; ++k) {
            float4 w = wr[k], z = zr[k];
            acc += w.x * z.x + w.y * z.y + w.z * z.z + w.w * z.w;
        }
        out[b * OUTC + tid] = acc + b2[tid];
    }
}

extern "C" void kernel_launch(void* const* d_in, const int* in_sizes, int n_in,
                              void* d_out, int out_size) {
    const float* x    = (const float*)d_in[0];
    const int*   ids  = (const int*)  d_in[1];
    const float* gW1  = (const float*)d_in[2];
    const float* gb1  = (const float*)d_in[3];
    const float* glng = (const float*)d_in[4];
    const float* glnb = (const float*)d_in[5];
    const float* gW2  = (const float*)d_in[6];
    const float* gb2  = (const float*)d_in[7];
    const float* png  = (const float*)d_in[8];
    const float* pnb  = (const float*)d_in[9];
    const float* mW1  = (const float*)d_in[10];
    const float* mb1  = (const float*)d_in[11];
    const float* mlng = (const float*)d_in[12];
    const float* mlnb = (const float*)d_in[13];
    const float* mW2  = (const float*)d_in[14];
    const float* mb2  = (const float*)d_in[15];
    const int N = in_sizes[0] / D;
    const int tiles = (N + 127) / 128;

    cudaFuncSetAttribute(prep_x_pack, cudaFuncAttributeMaxDynamicSharedMemorySize, SMX);
    cudaFuncSetAttribute(prep_w_pack, cudaFuncAttributeMaxDynamicSharedMemorySize, SMW);

    prep_w_pack<<<16, 256, SMW>>>(gW1);
    prep_x_pack<<<tiles, 256, SMX>>>(x, N);
    gemm_k<<<dim3(4, tiles), 256>>>();
    ln_gate_k<<<(N + 7) / 8, 256>>>(gb1, glng, glnb, gW2, gb2, N);
    segoff_k<<<1, 512>>>(ids, N);
    segpool_k<<<B, 256>>>(x);
    poolln_k<<<B, 256>>>(png, pnb);
    cls_hidden_k<<<B, 256>>>(mW1, mb1, mlng, mlnb);
    logits_k<<<B, 256>>>(mW2, mb2, (float*)d_out);
}

// round 14
// speedup vs baseline: 1.0854x; 1.0854x over previous
#include <cuda_runtime.h>
#include <cuda_fp16.h>
#include <mma.h>
#include <cstdint>
using namespace nvcuda;

#define EPS 1e-5f
static constexpr int D = 512, COLS = 1024, B = 256, OUTC = 250, MAXT = 784;

__device__ float g_gate[MAXT * 128];
__device__ int   g_segoff[257];
__device__ float g_pooled[B * D];
__device__ float g_pn[B * D];
__device__ float g_z[B * COLS];
// fragment-packed operands: 16B per lane per fragment
__device__ uint4 g_pa[(size_t)MAXT * 32 * 8 * 32];    // [tile][ks 32][mf 8][lane]  (A fp16)
__device__ uint4 g_pb[32 * 64 * 32];                  // [ks 32][nf 64][lane]       (W fp16)

// ---------- prep_x_pack: fp32 x -> fp16 -> wmma A fragments (packed) ----------
static constexpr int XP = 264;                        // smem row stride (half elems)
static constexpr uint32_t SMX = 128u * XP * 2;        // 67584 bytes

__global__ __launch_bounds__(256) void prep_x_pack(const float* __restrict__ x, int n) {
    extern __shared__ char sm[];
    __half* sh = (__half*)sm;
    const int tile = blockIdx.x, tid = threadIdx.x, wid = tid >> 5, lane = tid & 31;
    for (int kh = 0; kh < 2; ++kh) {
        __syncthreads();
        for (int i = tid; i < 8192; i += 256) {          // 128 rows x 64 float4
            int r = i >> 6, c4 = i & 63;
            int row = tile * 128 + r;
            float4 v = (row < n) ? *(const float4*)(x + (size_t)row * 512 + kh * 256 + c4 * 4)
                                 : make_float4(0.f, 0.f, 0.f, 0.f);
            *(__half2*)(sh + r * XP + c4 * 4)     = __floats2half2_rn(v.x, v.y);
            *(__half2*)(sh + r * XP + c4 * 4 + 2) = __floats2half2_rn(v.z, v.w);
        }
        __syncthreads();
        for (int ks = 0; ks < 16; ++ks) {
            wmma::fragment<wmma::matrix_a, 16, 16, 16, __half, wmma::row_major> f;
            wmma::load_matrix_sync(f, sh + (wid * 16) * XP + ks * 16, XP);
            g_pa[(((size_t)tile * 32 + kh * 16 + ks) * 8 + wid) * 32 + lane] =
                *(const uint4*)&f.x[0];
        }
    }
}

// ---------- prep_w_pack: fp32 W[1024,512] -> fp16 -> wmma B fragments ----------
static constexpr int WP = 520;
static constexpr uint32_t SMW = 64u * WP * 2;         // 66560 bytes

__global__ __launch_bounds__(256) void prep_w_pack(const float* __restrict__ w) {
    extern __shared__ char sm[];
    __half* sh = (__half*)sm;
    const int cb = blockIdx.x, tid = threadIdx.x, wid = tid >> 5, lane = tid & 31;
    for (int i = tid; i < 8192; i += 256) {              // 64 cols x 128 float4 (K=512)
        int c = i >> 7, k4 = i & 127;
        float4 v = *(const float4*)(w + (size_t)(cb * 64 + c) * 512 + k4 * 4);
        *(__half2*)(sh + c * WP + k4 * 4)     = __floats2half2_rn(v.x, v.y);
        *(__half2*)(sh + c * WP + k4 * 4 + 2) = __floats2half2_rn(v.z, v.w);
    }
    __syncthreads();
    for (int idx = wid; idx < 128; idx += 8) {           // 4 nf x 32 ks
        int ks = idx & 31, nf = idx >> 5;
        wmma::fragment<wmma::matrix_b, 16, 16, 16, __half, wmma::col_major> f;
        wmma::load_matrix_sync(f, sh + nf * 16 * WP + ks * 16, WP);
        g_pb[((size_t)ks * 64 + cb * 4 + nf) * 32 + lane] = *(const uint4*)&f.x[0];
    }
}

// ---------- fused GEMM + bias + LN + ReLU + gate dot ----------
// CTA: 32 rows x 1024 cols, 8 warps (1m x 8n), warp tile 32x128. grid = padN/32.
static constexpr int YP = 1032;                        // smem y row stride (floats)
static constexpr uint32_t SMG = (32u * YP + 4 * 1024) * 4;   // 148480 bytes

__global__ __launch_bounds__(256, 1) void gemm_fused_k(
    const float* __restrict__ bias, const float* __restrict__ lng,
    const float* __restrict__ lnb, const float* __restrict__ W2,
    const float* __restrict__ b2)
{
    extern __shared__ char sm[];
    float* sy = (float*)sm;                            // [32][YP]
    float* sB = sy + 32 * YP;                          // bias
    float* sG = sB + 1024;                             // lng
    float* sN = sG + 1024;                             // lnb
    float* sW = sN + 1024;                             // W2

    const int g = blockIdx.x;                          // 32-row group
    const int tid = threadIdx.x, wid = tid >> 5, lane = tid & 31;
    const int tile = g >> 2, mfb = (g & 3) * 2, nfb = wid * 8;

    for (int i = tid; i < 1024; i += 256) {
        sB[i] = bias[i]; sG[i] = lng[i]; sN[i] = lnb[i]; sW[i] = W2[i];
    }

    wmma::fragment<wmma::accumulator, 16, 16, 16, float> acc[2][8];
    #pragma unroll
    for (int mt = 0; mt < 2; ++mt)
        #pragma unroll
        for (int nt = 0; nt < 8; ++nt) wmma::fill_fragment(acc[mt][nt], 0.f);

    const uint4* __restrict__ pa = g_pa + (size_t)tile * 32 * 8 * 32;
    const uint4* __restrict__ pb = g_pb;

    #pragma unroll 4
    for (int ks = 0; ks < 32; ++ks) {
        wmma::fragment<wmma::matrix_a, 16, 16, 16, __half, wmma::row_major> a[2];
        wmma::fragment<wmma::matrix_b, 16, 16, 16, __half, wmma::col_major> b[8];
        #pragma unroll
        for (int mt = 0; mt < 2; ++mt)
            *(uint4*)&a[mt].x[0] = __ldg(&pa[(ks * 8 + mfb + mt) * 32 + lane]);
        #pragma unroll
        for (int nt = 0; nt < 8; ++nt)
            *(uint4*)&b[nt].x[0] = __ldg(&pb[(ks * 64 + nfb + nt) * 32 + lane]);
        #pragma unroll
        for (int mt = 0; mt < 2; ++mt)
            #pragma unroll
            for (int nt = 0; nt < 8; ++nt)
                wmma::mma_sync(acc[mt][nt], a[mt], b[nt], acc[mt][nt]);
    }
    // accs -> smem y
    #pragma unroll
    for (int mt = 0; mt < 2; ++mt)
        #pragma unroll
        for (int nt = 0; nt < 8; ++nt)
            wmma::store_matrix_sync(sy + (mt * 16) * YP + wid * 128 + nt * 16,
                                    acc[mt][nt], YP, wmma::mem_row_major);
    __syncthreads();

    // LN + ReLU + gate dot; each warp owns 4 rows
    #pragma unroll
    for (int rr = 0; rr < 4; ++rr) {
        const int r = wid * 4 + rr;
        const float* yr = sy + r * YP;
        float s1 = 0.f, s2 = 0.f;
        #pragma unroll
        for (int j = 0; j < 32; ++j) {
            int c = j * 32 + lane;
            float v = yr[c] + sB[c];
            s1 += v; s2 += v * v;
        }
        #pragma unroll
        for (int o = 16; o > 0; o >>= 1) {
            s1 += __shfl_xor_sync(~0u, s1, o);
            s2 += __shfl_xor_sync(~0u, s2, o);
        }
        float mean = s1 * (1.f / 1024.f);
        float rstd = rsqrtf(fmaxf(s2 * (1.f / 1024.f) - mean * mean, 0.f) + EPS);
        float gd = 0.f;
        #pragma unroll
        for (int j = 0; j < 32; ++j) {
            int c = j * 32 + lane;
            float v = (yr[c] + sB[c] - mean) * rstd * sG[c] + sN[c];
            gd += fmaxf(v, 0.f) * sW[c];
        }
        #pragma unroll
        for (int o = 16; o > 0; o >>= 1) gd += __shfl_xor_sync(~0u, gd, o);
        if (lane == 0) g_gate[g * 32 + r] = gd + b2[0];
    }
}

// ---------- tail (proven) ----------
__global__ void segoff_k(const int* __restrict__ ids, int N) {
    int b = threadIdx.x; if (b > B) return;
    int lo = 0, hi = N;
    while (lo < hi) { int m = (lo + hi) >> 1; if (ids[m] < b) lo = m + 1; else hi = m; }
    g_segoff[b] = lo;
}
__global__ __launch_bounds__(256) void segpool_k(const float* __restrict__ x) {
    __shared__ float red[32], sw[256], s_m, s_i;
    const int b = blockIdx.x, tid = threadIdx.x, lane = tid & 31, warp = tid >> 5;
    const int s = g_segoff[b], e = g_segoff[b + 1];
    float m = -3.4e38f;
    for (int i = s + tid; i < e; i += 256) m = fmaxf(m, g_gate[i]);
    for (int o = 16; o > 0; o >>= 1) m = fmaxf(m, __shfl_xor_sync(~0u, m, o));
    if (lane == 0) red[warp] = m;
    __syncthreads();
    if (tid < 32) {
        float v = (tid < 8) ? red[tid] : -3.4e38f;
        for (int o = 4; o > 0; o >>= 1) v = fmaxf(v, __shfl_xor_sync(~0u, v, o));
        if (tid == 0) s_m = v;
    }
    __syncthreads(); m = s_m;
    float ss = 0.f;
    for (int i = s + tid; i < e; i += 256) ss += expf(g_gate[i] - m);
    for (int o = 16; o > 0; o >>= 1) ss += __shfl_xor_sync(~0u, ss, o);
    __syncthreads();
    if (lane == 0) red[warp] = ss;
    __syncthreads();
    if (tid < 32) {
        float v = (tid < 8) ? red[tid] : 0.f;
        for (int o = 4; o > 0; o >>= 1) v += __shfl_xor_sync(~0u, v, o);
        if (tid == 0) s_i = (v > 0.f) ? 1.f / v : 0.f;
    }
    __syncthreads();
    const float inv = s_i;
    float2 acc = make_float2(0.f, 0.f);
    for (int base = s; base < e; base += 256) {
        int i = base + tid;
        sw[tid] = (i < e) ? expf(g_gate[i] - m) * inv : 0.f;
        __syncthreads();
        int cnt = min(256, e - base);
        #pragma unroll 4
        for (int r = 0; r < cnt; ++r) {
            float w = sw[r];
            float2 xv = *(const float2*)(x + (size_t)(base + r) * D + 2 * tid);
            acc.x += w * xv.x; acc.y += w * xv.y;
        }
        __syncthreads();
    }
    *(float2*)(g_pooled + b * D + 2 * tid) = acc;
}
__global__ __launch_bounds__(256) void poolln_k(const float* __restrict__ g, const float* __restrict__ bt) {
    __shared__ float red[64]; __shared__ float sm, sr;
    const int b = blockIdx.x, tid = threadIdx.x, lane = tid & 31, warp = tid >> 5;
    float v0 = g_pooled[b * D + tid], v1 = g_pooled[b * D + 256 + tid];
    float s1 = v0 + v1, s2 = v0 * v0 + v1 * v1;
    for (int o = 16; o > 0; o >>= 1) { s1 += __shfl_xor_sync(~0u, s1, o); s2 += __shfl_xor_sync(~0u, s2, o); }
    if (lane == 0) { red[warp] = s1; red[8 + warp] = s2; }
    __syncthreads();
    if (tid < 32) {
        float a1 = (tid < 8) ? red[tid] : 0.f, a2 = (tid < 8) ? red[8 + tid] : 0.f;
        for (int o = 4; o > 0; o >>= 1) { a1 += __shfl_xor_sync(~0u, a1, o); a2 += __shfl_xor_sync(~0u, a2, o); }
        if (tid == 0) {
            float mn = a1 * (1.f / D);
            sm = mn; sr = rsqrtf(fmaxf(a2 * (1.f / D) - mn * mn, 0.f) + EPS);
        }
    }
    __syncthreads();
    g_pn[b * D + tid]       = (v0 - sm) * sr * g[tid]       + bt[tid];
    g_pn[b * D + 256 + tid] = (v1 - sm) * sr * g[tid + 256] + bt[tid + 256];
}
__global__ __launch_bounds__(256) void cls_hidden_k(const float* __restrict__ W1, const float* __restrict__ b1,
                                                    const float* __restrict__ g, const float* __restrict__ bt) {
    __shared__ float sp[512]; __shared__ float red[64]; __shared__ float sm, sr;
    const int b = blockIdx.x, tid = threadIdx.x, lane = tid & 31, warp = tid >> 5;
    for (int i = tid; i < 512; i += 256) sp[i] = g_pn[b * D + i];
    __syncthreads();
    float v[4]; float s1 = 0.f, s2 = 0.f;
    #pragma unroll
    for (int cc = 0; cc < 4; ++cc) {
        int c = tid * 4 + cc;
        const float4* w = (const float4*)(W1 + (size_t)c * 512);
        const float4* p = (const float4*)sp;
        float a = b1[c];
        #pragma unroll 4
        for (int k = 0; k < 128; ++k) {
            float4 wv = w[k], pv = p[k];
            a += wv.x * pv.x + wv.y * pv.y + wv.z * pv.z + wv.w * pv.w;
        }
        v[cc] = a; s1 += a; s2 += a * a;
    }
    for (int o = 16; o > 0; o >>= 1) { s1 += __shfl_xor_sync(~0u, s1, o); s2 += __shfl_xor_sync(~0u, s2, o); }
    if (lane == 0) { red[warp] = s1; red[8 + warp] = s2; }
    __syncthreads();
    if (tid < 32) {
        float a1 = (tid < 8) ? red[tid] : 0.f, a2 = (tid < 8) ? red[8 + tid] : 0.f;
        for (int o = 4; o > 0; o >>= 1) { a1 += __shfl_xor_sync(~0u, a1, o); a2 += __shfl_xor_sync(~0u, a2, o); }
        if (tid == 0) {
            float mn = a1 * (1.f / COLS);
            sm = mn; sr = rsqrtf(fmaxf(a2 * (1.f / COLS) - mn * mn, 0.f) + EPS);
        }
    }
    __syncthreads();
    #pragma unroll
    for (int cc = 0; cc < 4; ++cc) {
        int c = tid * 4 + cc;
        g_z[(size_t)b * COLS + c] = fmaxf((v[cc] - sm) * sr * g[c] + bt[c], 0.f);
    }
}
__global__ __launch_bounds__(256) void logits_k(const float* __restrict__ W2, const float* __restrict__ b2,
                                                float* __restrict__ out) {
    __shared__ float sz[COLS];
    const int b = blockIdx.x, tid = threadIdx.x;
    for (int i = tid; i < COLS; i += 256) sz[i] = g_z[(size_t)b * COLS + i];
    __syncthreads();
    if (tid < OUTC) {
        const float4* wr = (const float4*)(W2 + (size_t)tid * COLS);
        const float4* zr = (const float4*)sz;
        float acc = 0.f;
        #pragma unroll 4
        for (int k = 0; k < COLS / 4; ++k) {
            float4 w = wr[k], z = zr[k];
            acc += w.x * z.x + w.y * z.y + w.z * z.z + w.w * z.w;
        }
        out[b * OUTC + tid] = acc + b2[tid];
    }
}

extern "C" void kernel_launch(void* const* d_in, const int* in_sizes, int n_in,
                              void* d_out, int out_size) {
    const float* x    = (const float*)d_in[0];
    const int*   ids  = (const int*)  d_in[1];
    const float* gW1  = (const float*)d_in[2];
    const float* gb1  = (const float*)d_in[3];
    const float* glng = (const float*)d_in[4];
    const float* glnb = (const float*)d_in[5];
    const float* gW2  = (const float*)d_in[6];
    const float* gb2  = (const float*)d_in[7];
    const float* png  = (const float*)d_in[8];
    const float* pnb  = (const float*)d_in[9];
    const float* mW1  = (const float*)d_in[10];
    const float* mb1  = (const float*)d_in[11];
    const float* mlng = (const float*)d_in[12];
    const float* mlnb = (const float*)d_in[13];
    const float* mW2  = (const float*)d_in[14];
    const float* mb2  = (const float*)d_in[15];
    const int N = in_sizes[0] / D;
    const int tiles = (N + 127) / 128;

    cudaFuncSetAttribute(prep_x_pack, cudaFuncAttributeMaxDynamicSharedMemorySize, SMX);
    cudaFuncSetAttribute(prep_w_pack, cudaFuncAttributeMaxDynamicSharedMemorySize, SMW);
    cudaFuncSetAttribute(gemm_fused_k, cudaFuncAttributeMaxDynamicSharedMemorySize, SMG);

    prep_w_pack<<<16, 256, SMW>>>(gW1);
    prep_x_pack<<<tiles, 256, SMX>>>(x, N);
    gemm_fused_k<<<tiles * 4, 256, SMG>>>(gb1, glng, glnb, gW2, gb2);
    segoff_k<<<1, 512>>>(ids, N);
    segpool_k<<<B, 256>>>(x);
    poolln_k<<<B, 256>>>(png, pnb);
    cls_hidden_k<<<B, 256>>>(mW1, mb1, mlng, mlnb);
    logits_k<<<B, 256>>>(mW2, mb2, (float*)d_out);
}

// round 15
// speedup vs baseline: 1.1353x; 1.0460x over previous
#include <cuda_runtime.h>
#include <cuda_fp16.h>
#include <mma.h>
#include <cstdint>
using namespace nvcuda;

#define EPS 1e-5f
static constexpr int D = 512, COLS = 1024, B = 256, OUTC = 250, MAXT = 784;

__device__ float g_gate[MAXT * 128];
__device__ int   g_segoff[257];
__device__ float g_pooled[B * D];
__device__ float g_pn[B * D];
__device__ float g_z[B * COLS];
__device__ float g_y[(size_t)MAXT * 128 * 1024];
// fragment-packed operands: 16B per lane per fragment
__device__ uint4 g_pa[(size_t)MAXT * 32 * 8 * 32];    // [tile][ks 32][mf 8][lane]  (A fp16)
__device__ uint4 g_pb[32 * 64 * 32];                  // [ks 32][nf 64][lane]       (W fp16)

// ---------- prep_x_pack: fp32 x -> fp16 -> wmma A fragments (packed) ----------
static constexpr int XP = 264;                        // smem row stride (half elems)
static constexpr uint32_t SMX = 128u * XP * 2;        // 67584 bytes

__global__ __launch_bounds__(256) void prep_x_pack(const float* __restrict__ x, int n) {
    extern __shared__ char sm[];
    __half* sh = (__half*)sm;
    const int tile = blockIdx.x, tid = threadIdx.x, wid = tid >> 5, lane = tid & 31;
    for (int kh = 0; kh < 2; ++kh) {
        __syncthreads();
        for (int i = tid; i < 8192; i += 256) {          // 128 rows x 64 float4
            int r = i >> 6, c4 = i & 63;
            int row = tile * 128 + r;
            float4 v = (row < n) ? *(const float4*)(x + (size_t)row * 512 + kh * 256 + c4 * 4)
                                 : make_float4(0.f, 0.f, 0.f, 0.f);
            *(__half2*)(sh + r * XP + c4 * 4)     = __floats2half2_rn(v.x, v.y);
            *(__half2*)(sh + r * XP + c4 * 4 + 2) = __floats2half2_rn(v.z, v.w);
        }
        __syncthreads();
        for (int ks = 0; ks < 16; ++ks) {
            wmma::fragment<wmma::matrix_a, 16, 16, 16, __half, wmma::row_major> f;
            wmma::load_matrix_sync(f, sh + (wid * 16) * XP + ks * 16, XP);
            g_pa[(((size_t)tile * 32 + kh * 16 + ks) * 8 + wid) * 32 + lane] =
                *(const uint4*)&f.x[0];
        }
    }
}

// ---------- prep_w_pack: fp32 W[1024,512] -> fp16 -> wmma B fragments ----------
static constexpr int WP = 520;
static constexpr uint32_t SMW = 64u * WP * 2;         // 66560 bytes

__global__ __launch_bounds__(256) void prep_w_pack(const float* __restrict__ w) {
    extern __shared__ char sm[];
    __half* sh = (__half*)sm;
    const int cb = blockIdx.x, tid = threadIdx.x, wid = tid >> 5, lane = tid & 31;
    for (int i = tid; i < 8192; i += 256) {              // 64 cols x 128 float4 (K=512)
        int c = i >> 7, k4 = i & 127;
        float4 v = *(const float4*)(w + (size_t)(cb * 64 + c) * 512 + k4 * 4);
        *(__half2*)(sh + c * WP + k4 * 4)     = __floats2half2_rn(v.x, v.y);
        *(__half2*)(sh + c * WP + k4 * 4 + 2) = __floats2half2_rn(v.z, v.w);
    }
    __syncthreads();
    for (int idx = wid; idx < 128; idx += 8) {           // 4 nf x 32 ks
        int ks = idx & 31, nf = idx >> 5;
        wmma::fragment<wmma::matrix_b, 16, 16, 16, __half, wmma::col_major> f;
        wmma::load_matrix_sync(f, sh + nf * 16 * WP + ks * 16, WP);
        g_pb[((size_t)ks * 64 + cb * 4 + nf) * 32 + lane] = *(const uint4*)&f.x[0];
    }
}

// ---------- phase A GEMM: fragment-direct fp16, 2 CTAs/SM for latency hiding ----------
// CTA 128x128 (8 warps, 4m x 2n), warp tile 32x64. grid (8, tiles).
__global__ __launch_bounds__(256, 2) void gemm_k() {
    const int cb = blockIdx.x, tile = blockIdx.y;
    const int wid = threadIdx.x >> 5, lane = threadIdx.x & 31;
    const int wm = wid & 3, wn = wid >> 2;
    const int mfb = wm * 2, nfb = cb * 8 + wn * 4;

    wmma::fragment<wmma::accumulator, 16, 16, 16, float> acc[2][4];
    #pragma unroll
    for (int mt = 0; mt < 2; ++mt)
        #pragma unroll
        for (int nt = 0; nt < 4; ++nt) wmma::fill_fragment(acc[mt][nt], 0.f);

    const uint4* __restrict__ pa = g_pa + (size_t)tile * 32 * 8 * 32;
    const uint4* __restrict__ pb = g_pb;

    #pragma unroll 4
    for (int ks = 0; ks < 32; ++ks) {
        wmma::fragment<wmma::matrix_a, 16, 16, 16, __half, wmma::row_major> a[2];
        wmma::fragment<wmma::matrix_b, 16, 16, 16, __half, wmma::col_major> b[4];
        #pragma unroll
        for (int mt = 0; mt < 2; ++mt)
            *(uint4*)&a[mt].x[0] = __ldg(&pa[(ks * 8 + mfb + mt) * 32 + lane]);
        #pragma unroll
        for (int nt = 0; nt < 4; ++nt)
            *(uint4*)&b[nt].x[0] = __ldg(&pb[(ks * 64 + nfb + nt) * 32 + lane]);
        #pragma unroll
        for (int mt = 0; mt < 2; ++mt)
            #pragma unroll
            for (int nt = 0; nt < 4; ++nt)
                wmma::mma_sync(acc[mt][nt], a[mt], b[nt], acc[mt][nt]);
    }
    #pragma unroll
    for (int mt = 0; mt < 2; ++mt)
        #pragma unroll
        for (int nt = 0; nt < 4; ++nt) {
            size_t row0 = (size_t)tile * 128 + wm * 32 + mt * 16;
            int col0 = cb * 128 + wn * 64 + nt * 16;
            wmma::store_matrix_sync(g_y + row0 * 1024 + col0, acc[mt][nt], 1024,
                                    wmma::mem_row_major);
        }
}

// ---------- LN + ReLU + gate dot (one warp per row) ----------
__global__ __launch_bounds__(256) void ln_gate_k(
    const float* __restrict__ bias, const float* __restrict__ lng,
    const float* __restrict__ lnb, const float* __restrict__ W2,
    const float* __restrict__ b2, int N)
{
    const int row = blockIdx.x * 8 + (threadIdx.x >> 5);
    if (row >= N) return;
    const int lane = threadIdx.x & 31;
    const float4* yr = (const float4*)(g_y + (size_t)row * 1024);
    const float4* b4 = (const float4*)bias;
    float4 v[8]; float s1 = 0.f, s2 = 0.f;
    #pragma unroll
    for (int j = 0; j < 8; ++j) {
        int i = j * 32 + lane;
        float4 t = yr[i], bb = b4[i];
        t.x += bb.x; t.y += bb.y; t.z += bb.z; t.w += bb.w;
        v[j] = t;
        s1 += t.x + t.y + t.z + t.w;
        s2 += t.x * t.x + t.y * t.y + t.z * t.z + t.w * t.w;
    }
    #pragma unroll
    for (int o = 16; o > 0; o >>= 1) {
        s1 += __shfl_xor_sync(~0u, s1, o);
        s2 += __shfl_xor_sync(~0u, s2, o);
    }
    float mean = s1 * (1.f / 1024.f);
    float rstd = rsqrtf(fmaxf(s2 * (1.f / 1024.f) - mean * mean, 0.f) + EPS);
    float gd = 0.f;
    #pragma unroll
    for (int j = 0; j < 8; ++j) {
        int i = j * 32 + lane;
        float4 g = ((const float4*)lng)[i], lb = ((const float4*)lnb)[i],
               w = ((const float4*)W2)[i];
        float t;
        t = (v[j].x - mean) * rstd * g.x + lb.x; gd += fmaxf(t, 0.f) * w.x;
        t = (v[j].y - mean) * rstd * g.y + lb.y; gd += fmaxf(t, 0.f) * w.y;
        t = (v[j].z - mean) * rstd * g.z + lb.z; gd += fmaxf(t, 0.f) * w.z;
        t = (v[j].w - mean) * rstd * g.w + lb.w; gd += fmaxf(t, 0.f) * w.w;
    }
    #pragma unroll
    for (int o = 16; o > 0; o >>= 1) gd += __shfl_xor_sync(~0u, gd, o);
    if (lane == 0) g_gate[row] = gd + b2[0];
}

// ---------- tail (proven) ----------
__global__ void segoff_k(const int* __restrict__ ids, int N) {
    int b = threadIdx.x; if (b > B) return;
    int lo = 0, hi = N;
    while (lo < hi) { int m = (lo + hi) >> 1; if (ids[m] < b) lo = m + 1; else hi = m; }
    g_segoff[b] = lo;
}
__global__ __launch_bounds__(256) void segpool_k(const float* __restrict__ x) {
    __shared__ float red[32], sw[256], s_m, s_i;
    const int b = blockIdx.x, tid = threadIdx.x, lane = tid & 31, warp = tid >> 5;
    const int s = g_segoff[b], e = g_segoff[b + 1];
    float m = -3.4e38f;
    for (int i = s + tid; i < e; i += 256) m = fmaxf(m, g_gate[i]);
    for (int o = 16; o > 0; o >>= 1) m = fmaxf(m, __shfl_xor_sync(~0u, m, o));
    if (lane == 0) red[warp] = m;
    __syncthreads();
    if (tid < 32) {
        float v = (tid < 8) ? red[tid] : -3.4e38f;
        for (int o = 4; o > 0; o >>= 1) v = fmaxf(v, __shfl_xor_sync(~0u, v, o));
        if (tid == 0) s_m = v;
    }
    __syncthreads(); m = s_m;
    float ss = 0.f;
    for (int i = s + tid; i < e; i += 256) ss += expf(g_gate[i] - m);
    for (int o = 16; o > 0; o >>= 1) ss += __shfl_xor_sync(~0u, ss, o);
    __syncthreads();
    if (lane == 0) red[warp] = ss;
    __syncthreads();
    if (tid < 32) {
        float v = (tid < 8) ? red[tid] : 0.f;
        for (int o = 4; o > 0; o >>= 1) v += __shfl_xor_sync(~0u, v, o);
        if (tid == 0) s_i = (v > 0.f) ? 1.f / v : 0.f;
    }
    __syncthreads();
    const float inv = s_i;
    float2 acc = make_float2(0.f, 0.f);
    for (int base = s; base < e; base += 256) {
        int i = base + tid;
        sw[tid] = (i < e) ? expf(g_gate[i] - m) * inv : 0.f;
        __syncthreads();
        int cnt = min(256, e - base);
        #pragma unroll 4
        for (int r = 0; r < cnt; ++r) {
            float w = sw[r];
            float2 xv = *(const float2*)(x + (size_t)(base + r) * D + 2 * tid);
            acc.x += w * xv.x; acc.y += w * xv.y;
        }
        __syncthreads();
    }
    *(float2*)(g_pooled + b * D + 2 * tid) = acc;
}
__global__ __launch_bounds__(256) void poolln_k(const float* __restrict__ g, const float* __restrict__ bt) {
    __shared__ float red[64]; __shared__ float sm, sr;
    const int b = blockIdx.x, tid = threadIdx.x, lane = tid & 31, warp = tid >> 5;
    float v0 = g_pooled[b * D + tid], v1 = g_pooled[b * D + 256 + tid];
    float s1 = v0 + v1, s2 = v0 * v0 + v1 * v1;
    for (int o = 16; o > 0; o >>= 1) { s1 += __shfl_xor_sync(~0u, s1, o); s2 += __shfl_xor_sync(~0u, s2, o); }
    if (lane == 0) { red[warp] = s1; red[8 + warp] = s2; }
    __syncthreads();
    if (tid < 32) {
        float a1 = (tid < 8) ? red[tid] : 0.f, a2 = (tid < 8) ? red[8 + tid] : 0.f;
        for (int o = 4; o > 0; o >>= 1) { a1 += __shfl_xor_sync(~0u, a1, o); a2 += __shfl_xor_sync(~0u, a2, o); }
        if (tid == 0) {
            float mn = a1 * (1.f / D);
            sm = mn; sr = rsqrtf(fmaxf(a2 * (1.f / D) - mn * mn, 0.f) + EPS);
        }
    }
    __syncthreads();
    g_pn[b * D + tid]       = (v0 - sm) * sr * g[tid]       + bt[tid];
    g_pn[b * D + 256 + tid] = (v1 - sm) * sr * g[tid + 256] + bt[tid + 256];
}
__global__ __launch_bounds__(256) void cls_hidden_k(const float* __restrict__ W1, const float* __restrict__ b1,
                                                    const float* __restrict__ g, const float* __restrict__ bt) {
    __shared__ float sp[512]; __shared__ float red[64]; __shared__ float sm, sr;
    const int b = blockIdx.x, tid = threadIdx.x, lane = tid & 31, warp = tid >> 5;
    for (int i = tid; i < 512; i += 256) sp[i] = g_pn[b * D + i];
    __syncthreads();
    float v[4]; float s1 = 0.f, s2 = 0.f;
    #pragma unroll
    for (int cc = 0; cc < 4; ++cc) {
        int c = tid * 4 + cc;
        const float4* w = (const float4*)(W1 + (size_t)c * 512);
        const float4* p = (const float4*)sp;
        float a = b1[c];
        #pragma unroll 4
        for (int k = 0; k < 128; ++k) {
            float4 wv = w[k], pv = p[k];
            a += wv.x * pv.x + wv.y * pv.y + wv.z * pv.z + wv.w * pv.w;
        }
        v[cc] = a; s1 += a; s2 += a * a;
    }
    for (int o = 16; o > 0; o >>= 1) { s1 += __shfl_xor_sync(~0u, s1, o); s2 += __shfl_xor_sync(~0u, s2, o); }
    if (lane == 0) { red[warp] = s1; red[8 + warp] = s2; }
    __syncthreads();
    if (tid < 32) {
        float a1 = (tid < 8) ? red[tid] : 0.f, a2 = (tid < 8) ? red[8 + tid] : 0.f;
        for (int o = 4; o > 0; o >>= 1) { a1 += __shfl_xor_sync(~0u, a1, o); a2 += __shfl_xor_sync(~0u, a2, o); }
        if (tid == 0) {
            float mn = a1 * (1.f / COLS);
            sm = mn; sr = rsqrtf(fmaxf(a2 * (1.f / COLS) - mn * mn, 0.f) + EPS);
        }
    }
    __syncthreads();
    #pragma unroll
    for (int cc = 0; cc < 4; ++cc) {
        int c = tid * 4 + cc;
        g_z[(size_t)b * COLS + c] = fmaxf((v[cc] - sm) * sr * g[c] + bt[c], 0.f);
    }
}
__global__ __launch_bounds__(256) void logits_k(const float* __restrict__ W2, const float* __restrict__ b2,
                                                float* __restrict__ out) {
    __shared__ float sz[COLS];
    const int b = blockIdx.x, tid = threadIdx.x;
    for (int i = tid; i < COLS; i += 256) sz[i] = g_z[(size_t)b * COLS + i];
    __syncthreads();
    if (tid < OUTC) {
        const float4* wr = (const float4*)(W2 + (size_t)tid * COLS);
        const float4* zr = (const float4*)sz;
        float acc = 0.f;
        #pragma unroll 4
        for (int k = 0; k < COLS / 4; ++k) {
            float4 w = wr[k], z = zr[k];
            acc += w.x * z.x + w.y * z.y + w.z * z.z + w.w * z.w;
        }
        out[b * OUTC + tid] = acc + b2[tid];
    }
}

extern "C" void kernel_launch(void* const* d_in, const int* in_sizes, int n_in,
                              void* d_out, int out_size) {
    const float* x    = (const float*)d_in[0];
    const int*   ids  = (const int*)  d_in[1];
    const float* gW1  = (const float*)d_in[2];
    const float* gb1  = (const float*)d_in[3];
    const float* glng = (const float*)d_in[4];
    const float* glnb = (const float*)d_in[5];
    const float* gW2  = (const float*)d_in[6];
    const float* gb2  = (const float*)d_in[7];
    const float* png  = (const float*)d_in[8];
    const float* pnb  = (const float*)d_in[9];
    const float* mW1  = (const float*)d_in[10];
    const float* mb1  = (const float*)d_in[11];
    const float* mlng = (const float*)d_in[12];
    const float* mlnb = (const float*)d_in[13];
    const float* mW2  = (const float*)d_in[14];
    const float* mb2  = (const float*)d_in[15];
    const int N = in_sizes[0] / D;
    const int tiles = (N + 127) / 128;

    cudaFuncSetAttribute(prep_x_pack, cudaFuncAttributeMaxDynamicSharedMemorySize, SMX);
    cudaFuncSetAttribute(prep_w_pack, cudaFuncAttributeMaxDynamicSharedMemorySize, SMW);

    prep_w_pack<<<16, 256, SMW>>>(gW1);
    prep_x_pack<<<tiles, 256, SMX>>>(x, N);
    gemm_k<<<dim3(8, tiles), 256>>>();
    ln_gate_k<<<(N + 7) / 8, 256>>>(gb1, glng, glnb, gW2, gb2, N);
    segoff_k<<<1, 512>>>(ids, N);
    segpool_k<<<B, 256>>>(x);
    poolln_k<<<B, 256>>>(png, pnb);
    cls_hidden_k<<<B, 256>>>(mW1, mb1, mlng, mlnb);
    logits_k<<<B, 256>>>(mW2, mb2, (float*)d_out);
}